// round 8
// baseline (speedup 1.0000x reference)
#include <cuda_runtime.h>

#define BATCH 16
#define SEQY 2048
#define SEQX 2048
#define DIM 128
#define TY 64
#define TX 64
#define NTHREADS 256
#define NTILES (SEQX / TX)   // 32
#define YBLK (SEQY / TY)     // 32

// padded pitches (in floats)
#define YT_PITCH 68   // Yt[d][y], 272B rows -> 16B aligned, conflict-free LDS.128
#define XT_PITCH 68   // Xt[d][x]
#define XR_PITCH 132  // Xr[x][d], 528B rows
#define PT_PITCH 65   // Pt[x][y] (scalar access, odd pitch kills conflicts)

struct SmemLayout {
    float Yt[DIM * YT_PITCH];   // 34816 B
    float Xt[DIM * XT_PITCH];   // 34816 B
    float Xr[TX * XR_PITCH];    // 33792 B
    float Pt[TX * PT_PITCH];    // 16640 B
    float mrow[TY];
    float lrow[TY];
    float frow[TY];
    float red[16 * DIM];        // 8192 B
};  // ~129 KB total

__device__ float g_partial[BATCH * YBLK * DIM];
__device__ float g_ysum[BATCH * DIM];

// ---------------------------------------------------------------------------
// Main fused kernel: one block per (batch, 64-row y tile). Online softmax.
// ---------------------------------------------------------------------------
__global__ void __launch_bounds__(NTHREADS, 1)
attn_main_kernel(const float* __restrict__ Xg, const float* __restrict__ Yg)
{
    extern __shared__ float smem_f[];
    SmemLayout* sm = reinterpret_cast<SmemLayout*>(smem_f);
    const int tid = threadIdx.x;
    const int b   = blockIdx.x / YBLK;
    const int yb  = blockIdx.x % YBLK;

    const float* Ybase = Yg + ((size_t)(b * SEQY + yb * TY)) * DIM;
    const float* Xbase = Xg + (size_t)b * SEQX * DIM;

    // Load Y tile transposed: Yt[d][y] (one-time; store conflicts don't matter)
    #pragma unroll
    for (int it = 0; it < (TY * DIM) / NTHREADS; ++it) {
        int e = tid + it * NTHREADS;
        int y = e >> 7;
        int d = e & 127;
        sm->Yt[d * YT_PITCH + y] = Ybase[e];
    }
    if (tid < TY) { sm->mrow[tid] = -3.0e38f; sm->lrow[tid] = 0.f; }

    const int ty = tid >> 4;   // 16 y-groups of 4 rows
    const int tx = tid & 15;   // 16 x-groups of 4 cols (S) / 16 d-groups (PV)

    float acc[4][8];           // PV accumulator: 4 y-rows x 8 d (d = tx + 16*j)
    #pragma unroll
    for (int i = 0; i < 4; ++i)
        #pragma unroll
        for (int j = 0; j < 8; ++j) acc[i][j] = 0.f;

    for (int t = 0; t < NTILES; ++t) {
        __syncthreads();   // previous PV done before overwriting X tiles

        // Load X tile (64x128) into both layouts; gmem reads L2-resident.
        const float* Xtile = Xbase + (size_t)t * (TX * DIM);
        #pragma unroll
        for (int it = 0; it < (TX * DIM) / NTHREADS; ++it) {
            int e = tid + it * NTHREADS;
            int x = e >> 7;
            int d = e & 127;
            float v = Xtile[e];
            sm->Xt[d * XT_PITCH + x] = v;
            sm->Xr[x * XR_PITCH + d] = v;
        }
        __syncthreads();

        // ---- S = Y_tile @ X_tile^T  (outer product over k = d) ----
        float s[4][4];
        #pragma unroll
        for (int i = 0; i < 4; ++i)
            #pragma unroll
            for (int j = 0; j < 4; ++j) s[i][j] = 0.f;

        const float* ytp = sm->Yt + ty * 4;
        const float* xtp = sm->Xt + tx * 4;
        #pragma unroll 8
        for (int k = 0; k < DIM; ++k) {
            float4 a  = *reinterpret_cast<const float4*>(ytp + k * YT_PITCH);
            float4 bb = *reinterpret_cast<const float4*>(xtp + k * XT_PITCH);
            float av[4] = {a.x, a.y, a.z, a.w};
            float bv[4] = {bb.x, bb.y, bb.z, bb.w};
            #pragma unroll
            for (int i = 0; i < 4; ++i)
                #pragma unroll
                for (int j = 0; j < 4; ++j)
                    s[i][j] = fmaf(av[i], bv[j], s[i][j]);
        }
        // Store S transposed: Pt[x][y]
        #pragma unroll
        for (int j = 0; j < 4; ++j)
            #pragma unroll
            for (int i = 0; i < 4; ++i)
                sm->Pt[(tx * 4 + j) * PT_PITCH + (ty * 4 + i)] = s[i][j];

        __syncthreads();

        // ---- online softmax over this tile: 4 threads per row ----
        {
            const int r = tid >> 2;   // row 0..63
            const int q = tid & 3;    // quarter of the 64 x values
            float v[16];
            float mx = -3.0e38f;
            #pragma unroll
            for (int u = 0; u < 16; ++u) {
                float vv = sm->Pt[(q * 16 + u) * PT_PITCH + r];
                v[u] = vv;
                mx = fmaxf(mx, vv);
            }
            mx = fmaxf(mx, __shfl_xor_sync(0xffffffffu, mx, 1));
            mx = fmaxf(mx, __shfl_xor_sync(0xffffffffu, mx, 2));
            float m_old = sm->mrow[r];
            float m_new = fmaxf(m_old, mx);
            float sum = 0.f;
            #pragma unroll
            for (int u = 0; u < 16; ++u) {
                float p = __expf(v[u] - m_new);
                sum += p;
                sm->Pt[(q * 16 + u) * PT_PITCH + r] = p;
            }
            sum += __shfl_xor_sync(0xffffffffu, sum, 1);
            sum += __shfl_xor_sync(0xffffffffu, sum, 2);
            if (q == 0) {
                float f = __expf(m_old - m_new);   // exp(-huge) -> 0, no NaN
                sm->lrow[r] = sm->lrow[r] * f + sum;
                sm->mrow[r] = m_new;
                sm->frow[r] = f;
            }
        }
        __syncthreads();

        // ---- acc = acc * fac + P @ X_tile ----
        {
            float f[4];
            #pragma unroll
            for (int i = 0; i < 4; ++i) f[i] = sm->frow[ty * 4 + i];
            #pragma unroll
            for (int i = 0; i < 4; ++i)
                #pragma unroll
                for (int j = 0; j < 8; ++j) acc[i][j] *= f[i];

            const float* ptp = sm->Pt + ty * 4;
            const float* xrp = sm->Xr + tx;     // this thread owns d = tx + 16*j
            #pragma unroll 4
            for (int k = 0; k < TX; ++k) {
                float a0 = ptp[k * PT_PITCH + 0];
                float a1 = ptp[k * PT_PITCH + 1];
                float a2 = ptp[k * PT_PITCH + 2];
                float a3 = ptp[k * PT_PITCH + 3];
                #pragma unroll
                for (int j = 0; j < 8; ++j) {
                    float bvv = xrp[k * XR_PITCH + 16 * j];
                    acc[0][j] = fmaf(a0, bvv, acc[0][j]);
                    acc[1][j] = fmaf(a1, bvv, acc[1][j]);
                    acc[2][j] = fmaf(a2, bvv, acc[2][j]);
                    acc[3][j] = fmaf(a3, bvv, acc[3][j]);
                }
            }
        }
    }

    // ---- epilogue: sum_y acc[y][d] / l[y] over this block's 64 rows ----
    float inv[4];
    #pragma unroll
    for (int i = 0; i < 4; ++i) inv[i] = 1.0f / sm->lrow[ty * 4 + i];
    #pragma unroll
    for (int j = 0; j < 8; ++j) {
        float p = acc[0][j] * inv[0] + acc[1][j] * inv[1]
                + acc[2][j] * inv[2] + acc[3][j] * inv[3];
        sm->red[ty * DIM + tx + 16 * j] = p;
    }
    __syncthreads();
    if (tid < DIM) {
        float ssum = 0.f;
        #pragma unroll
        for (int g = 0; g < 16; ++g) ssum += sm->red[g * DIM + tid];
        g_partial[blockIdx.x * DIM + tid] = ssum;
    }
}

// ---------------------------------------------------------------------------
// ysum[b][d] = sum_y Y[b][y][d]   (visual = ysum . x / SY, rank-1 trick)
// ---------------------------------------------------------------------------
__global__ void ysum_kernel(const float* __restrict__ Yg)
{
    __shared__ float buf[2 * DIM];
    int b = blockIdx.x;
    int d = threadIdx.x & 127;
    int h = threadIdx.x >> 7;   // 0/1: even/odd y
    const float* p = Yg + ((size_t)b * SEQY + h) * DIM + d;
    float s0 = 0.f, s1 = 0.f, s2 = 0.f, s3 = 0.f;
    for (int y = 0; y < SEQY / 2; y += 4) {
        s0 += p[(size_t)(2 * (y + 0)) * DIM];
        s1 += p[(size_t)(2 * (y + 1)) * DIM];
        s2 += p[(size_t)(2 * (y + 2)) * DIM];
        s3 += p[(size_t)(2 * (y + 3)) * DIM];
    }
    buf[h * DIM + d] = (s0 + s1) + (s2 + s3);
    __syncthreads();
    if (h == 0) g_ysum[b * DIM + d] = buf[d] + buf[DIM + d];
}

// ---------------------------------------------------------------------------
// visual[b][x] = dot(ysum[b], X[b][x]) / SY   (one warp per x)
// ---------------------------------------------------------------------------
__global__ void visual_kernel(const float* __restrict__ Xg, float* __restrict__ out)
{
    __shared__ float ys[DIM];
    const int bpb = SEQX / 8;    // blocks per batch
    int b  = blockIdx.x / bpb;
    int x0 = (blockIdx.x % bpb) * 8;
    if (threadIdx.x < DIM) ys[threadIdx.x] = g_ysum[b * DIM + threadIdx.x];
    __syncthreads();
    int w    = threadIdx.x >> 5;
    int lane = threadIdx.x & 31;
    int x    = x0 + w;
    const float* xp = Xg + ((size_t)b * SEQX + x) * DIM + lane * 4;
    float4 xv = *reinterpret_cast<const float4*>(xp);
    float4 yv = *reinterpret_cast<const float4*>(ys + lane * 4);
    float sdot = xv.x * yv.x + xv.y * yv.y + xv.z * yv.z + xv.w * yv.w;
    #pragma unroll
    for (int o = 16; o > 0; o >>= 1)
        sdot += __shfl_xor_sync(0xffffffffu, sdot, o);
    if (lane == 0) out[(size_t)b * SEQX + x] = sdot * (1.0f / SEQY);
}

// ---------------------------------------------------------------------------
// out[b][d] = sum over y-blocks of partials / SY
// ---------------------------------------------------------------------------
__global__ void outred_kernel(float* __restrict__ out)
{
    int b = blockIdx.x;
    int d = threadIdx.x;
    float s = 0.f;
    #pragma unroll 8
    for (int g = 0; g < YBLK; ++g)
        s += g_partial[(b * YBLK + g) * DIM + d];
    out[(size_t)BATCH * SEQX + b * DIM + d] = s * (1.0f / SEQY);
}

extern "C" void kernel_launch(void* const* d_in, const int* in_sizes, int n_in,
                              void* d_out, int out_size)
{
    const float* X = (const float*)d_in[0];   // input_x [B, SX, D]
    const float* Y = (const float*)d_in[1];   // input_y [B, SY, D]
    float* out = (float*)d_out;               // [B*SX visual | B*D out]

    (void)in_sizes; (void)n_in; (void)out_size;

    cudaFuncSetAttribute(attn_main_kernel,
                         cudaFuncAttributeMaxDynamicSharedMemorySize,
                         (int)sizeof(SmemLayout));

    ysum_kernel<<<BATCH, 256>>>(Y);
    visual_kernel<<<BATCH * SEQX / 8, 256>>>(X, out);
    attn_main_kernel<<<BATCH * YBLK, NTHREADS, sizeof(SmemLayout)>>>(X, Y);
    outred_kernel<<<BATCH, DIM>>>(out);
}

// round 10
// speedup vs baseline: 2.3133x; 2.3133x over previous
#include <cuda_runtime.h>
#include <cuda_bf16.h>
#include <cstdint>

#define BATCH 16
#define SEQY 2048
#define SEQX 2048
#define DIM 128
#define TM 128                  // y rows per CTA
#define TN 64                   // x cols per tile
#define NT (SEQX / TN)          // 32 x-tiles
#define YB (SEQY / TM)          // 16 y-blocks per batch
#define NTHREADS 256

// smem pitch: 136 bf16 = 272 B = 68 words -> bank(row r, word c) = (4r+c)%32, conflict-free
#define PITCH_B 272

// smem byte offsets
#define OFF_YHI   0u
#define OFF_YLO   34816u
#define OFF_XHI   69632u
#define OFF_XLO   87040u
#define OFF_LP    104448u      // [2][128] f32
#define OFF_LROW  105472u      // [128] f32 (stores 1/l)
#define OFF_CSP   105984u      // [4][64] f32
#define SM_BYTES  107008u
#define DLT_YLO   34816u       // OFF_YLO - OFF_YHI
#define DLT_XLO   17408u

__device__ float g_cpart[BATCH * YB * SEQX];   // 2 MB
__device__ float g_opart[BATCH * 8 * DIM];
__device__ float g_ysum[BATCH * DIM];

static __device__ __forceinline__ uint32_t smem_u32_of(const void* p) {
    uint32_t a;
    asm("{ .reg .u64 t; cvta.to.shared.u64 t, %1; cvt.u32.u64 %0, t; }" : "=r"(a) : "l"(p));
    return a;
}
static __device__ __forceinline__ uint32_t lds32(uint32_t a) {
    uint32_t v;
    asm volatile("ld.shared.b32 %0, [%1];" : "=r"(v) : "r"(a));
    return v;
}
static __device__ __forceinline__ float lds32f(uint32_t a) {
    float v;
    asm volatile("ld.shared.f32 %0, [%1];" : "=f"(v) : "r"(a));
    return v;
}
static __device__ __forceinline__ void sts32(uint32_t a, uint32_t v) {
    asm volatile("st.shared.b32 [%0], %1;" :: "r"(a), "r"(v));
}

// hi = truncate-to-bf16 (upper 16 bits); packed word: low half = even elem, high = odd elem
static __device__ __forceinline__ uint32_t hi_pack(float a, float b) {
    uint32_t r;
    asm("prmt.b32 %0, %1, %2, 0x7632;" : "=r"(r)
        : "r"(__float_as_uint(a)), "r"(__float_as_uint(b)));
    return r;
}
static __device__ __forceinline__ uint32_t lo_pack(float a, float b) {
    float ah = __uint_as_float(__float_as_uint(a) & 0xffff0000u);
    float bh = __uint_as_float(__float_as_uint(b) & 0xffff0000u);
    uint32_t r;  // first src -> high half, second -> low half
    asm("cvt.rn.bf16x2.f32 %0, %1, %2;" : "=r"(r) : "f"(b - bh), "f"(a - ah));
    return r;
}

#define MMA_BF16(D, A, B0, B1)                                              \
    asm volatile("mma.sync.aligned.m16n8k16.row.col.f32.bf16.bf16.f32 "     \
        "{%0,%1,%2,%3}, {%4,%5,%6,%7}, {%8,%9}, {%0,%1,%2,%3};"             \
        : "+f"((D)[0]), "+f"((D)[1]), "+f"((D)[2]), "+f"((D)[3])            \
        : "r"((A)[0]), "r"((A)[1]), "r"((A)[2]), "r"((A)[3]),               \
          "r"(B0), "r"(B1))

// ---------------------------------------------------------------------------
// Convert+store a 64x128 fp32 X tile into bf16 hi/lo smem (all 256 threads)
// ---------------------------------------------------------------------------
static __device__ __forceinline__ void load_xtile(const float* __restrict__ Xt,
                                                  uint32_t smb, int tid) {
    const int row = tid >> 2;
    const int kc  = (tid & 3) * 32;
    const float4* gp = reinterpret_cast<const float4*>(Xt + row * DIM + kc);
    uint32_t hb = smb + OFF_XHI + (uint32_t)row * PITCH_B + (uint32_t)kc * 2;
    #pragma unroll
    for (int i = 0; i < 8; ++i) {
        float4 v = gp[i];
        sts32(hb + i * 8,               hi_pack(v.x, v.y));
        sts32(hb + i * 8 + 4,           hi_pack(v.z, v.w));
        sts32(hb + i * 8 + DLT_XLO,     lo_pack(v.x, v.y));
        sts32(hb + i * 8 + 4 + DLT_XLO, lo_pack(v.z, v.w));
    }
}

// ---------------------------------------------------------------------------
// S = Y_tile(128x128) @ X_tile(64x128)^T, bf16 3-pass split, warp tile 32x32
// ---------------------------------------------------------------------------
static __device__ __forceinline__ void compute_S(uint32_t aH, uint32_t bH,
                                                 float S[2][4][4]) {
    #pragma unroll
    for (int mb = 0; mb < 2; ++mb)
        #pragma unroll
        for (int nb = 0; nb < 4; ++nb)
            #pragma unroll
            for (int e = 0; e < 4; ++e) S[mb][nb][e] = 0.f;

    #pragma unroll
    for (int ks = 0; ks < 8; ++ks) {
        const uint32_t off = ks * 32;
        uint32_t Ah[2][4], Al[2][4];
        #pragma unroll
        for (int mb = 0; mb < 2; ++mb) {
            uint32_t r = aH + off + mb * (16 * PITCH_B);
            Ah[mb][0] = lds32(r);
            Ah[mb][1] = lds32(r + 8 * PITCH_B);
            Ah[mb][2] = lds32(r + 16);
            Ah[mb][3] = lds32(r + 8 * PITCH_B + 16);
            Al[mb][0] = lds32(r + DLT_YLO);
            Al[mb][1] = lds32(r + DLT_YLO + 8 * PITCH_B);
            Al[mb][2] = lds32(r + DLT_YLO + 16);
            Al[mb][3] = lds32(r + DLT_YLO + 8 * PITCH_B + 16);
        }
        #pragma unroll
        for (int nb = 0; nb < 4; ++nb) {
            uint32_t rb = bH + off + nb * (8 * PITCH_B);
            uint32_t b0 = lds32(rb);
            uint32_t b1 = lds32(rb + 16);
            uint32_t l0 = lds32(rb + DLT_XLO);
            uint32_t l1 = lds32(rb + DLT_XLO + 16);
            #pragma unroll
            for (int mb = 0; mb < 2; ++mb) {
                MMA_BF16(S[mb][nb], Ah[mb], b0, b1);   // hi*hi
                MMA_BF16(S[mb][nb], Ah[mb], l0, l1);   // hi*lo
                MMA_BF16(S[mb][nb], Al[mb], b0, b1);   // lo*hi
            }
        }
    }
}

// ---------------------------------------------------------------------------
// Main kernel: blockIdx = b*16 + yb. Two phases: row sums l, then c_x.
// ---------------------------------------------------------------------------
__global__ void __launch_bounds__(NTHREADS, 2)
attn_hmma_kernel(const float* __restrict__ Xg, const float* __restrict__ Yg)
{
    extern __shared__ char smem[];
    const uint32_t smb = smem_u32_of(smem);
    const int tid  = threadIdx.x;
    const int lane = tid & 31;
    const int wid  = tid >> 5;
    const int wm   = wid >> 1;     // 0..3: warp row group (32 rows)
    const int wn   = wid & 1;      // 0..1: warp col group (32 cols)
    const int g    = lane >> 2;    // 0..7
    const int c    = lane & 3;     // 0..3
    const int b    = blockIdx.x >> 4;
    const int yb   = blockIdx.x & 15;

    const float* Xb = Xg + (size_t)b * SEQX * DIM;

    // ---- Prologue: Y tile (128x128) -> bf16 hi/lo smem ----
    {
        const int row = tid >> 1;
        const int kc  = (tid & 1) * 64;
        const float4* gp = reinterpret_cast<const float4*>(
            Yg + ((size_t)(b * SEQY + yb * TM + row)) * DIM + kc);
        uint32_t hb = smb + OFF_YHI + (uint32_t)row * PITCH_B + (uint32_t)kc * 2;
        #pragma unroll
        for (int i = 0; i < 16; ++i) {
            float4 v = gp[i];
            sts32(hb + i * 8,               hi_pack(v.x, v.y));
            sts32(hb + i * 8 + 4,           hi_pack(v.z, v.w));
            sts32(hb + i * 8 + DLT_YLO,     lo_pack(v.x, v.y));
            sts32(hb + i * 8 + 4 + DLT_YLO, lo_pack(v.z, v.w));
        }
    }

    const uint32_t aH = smb + OFF_YHI + (uint32_t)(wm * 32 + g) * PITCH_B + 4u * c;
    const uint32_t bH = smb + OFF_XHI + (uint32_t)(wn * 32 + g) * PITCH_B + 4u * c;

    // ================= Phase 1: l[y] = sum_x exp(S) =================
    float rs[4] = {0.f, 0.f, 0.f, 0.f};   // rows: mb*2+h -> wm*32+mb*16+8h+g
    for (int t = 0; t < NT; ++t) {
        __syncthreads();
        load_xtile(Xb + (size_t)t * TN * DIM, smb, tid);
        __syncthreads();
        float S[2][4][4];
        compute_S(aH, bH, S);
        #pragma unroll
        for (int mb = 0; mb < 2; ++mb)
            #pragma unroll
            for (int h = 0; h < 2; ++h) {
                float e = 0.f;
                #pragma unroll
                for (int nb = 0; nb < 4; ++nb)
                    e += __expf(S[mb][nb][2 * h]) + __expf(S[mb][nb][2 * h + 1]);
                e += __shfl_xor_sync(0xffffffffu, e, 1);
                e += __shfl_xor_sync(0xffffffffu, e, 2);
                rs[mb * 2 + h] += e;
            }
    }
    if (c == 0) {
        #pragma unroll
        for (int mb = 0; mb < 2; ++mb)
            #pragma unroll
            for (int h = 0; h < 2; ++h) {
                int row = wm * 32 + mb * 16 + 8 * h + g;
                sts32(smb + OFF_LP + (uint32_t)(wn * 128 + row) * 4,
                      __float_as_uint(rs[mb * 2 + h]));
            }
    }
    __syncthreads();
    if (tid < 128) {
        float l = lds32f(smb + OFF_LP + tid * 4) +
                  lds32f(smb + OFF_LP + (128 + tid) * 4);
        sts32(smb + OFF_LROW + tid * 4, __float_as_uint(1.0f / l));
    }
    __syncthreads();

    float linv[4];
    #pragma unroll
    for (int mb = 0; mb < 2; ++mb)
        #pragma unroll
        for (int h = 0; h < 2; ++h)
            linv[mb * 2 + h] = lds32f(smb + OFF_LROW +
                (uint32_t)(wm * 32 + mb * 16 + 8 * h + g) * 4);

    // ================= Phase 2: c_x = sum_y exp(S)/l_y =================
    for (int t = 0; t < NT; ++t) {
        __syncthreads();
        load_xtile(Xb + (size_t)t * TN * DIM, smb, tid);
        __syncthreads();
        float S[2][4][4];
        compute_S(aH, bH, S);

        float cs[4][2];
        #pragma unroll
        for (int nb = 0; nb < 4; ++nb)
            #pragma unroll
            for (int e2 = 0; e2 < 2; ++e2) {
                float v = 0.f;
                #pragma unroll
                for (int mb = 0; mb < 2; ++mb)
                    v += __expf(S[mb][nb][e2])     * linv[2 * mb]
                       + __expf(S[mb][nb][e2 + 2]) * linv[2 * mb + 1];
                v += __shfl_xor_sync(0xffffffffu, v, 4);
                v += __shfl_xor_sync(0xffffffffu, v, 8);
                v += __shfl_xor_sync(0xffffffffu, v, 16);
                cs[nb][e2] = v;
            }
        if (lane < 4) {   // c = lane
            #pragma unroll
            for (int nb = 0; nb < 4; ++nb)
                #pragma unroll
                for (int e2 = 0; e2 < 2; ++e2)
                    sts32(smb + OFF_CSP +
                          (uint32_t)(wm * 64 + wn * 32 + nb * 8 + 2 * lane + e2) * 4,
                          __float_as_uint(cs[nb][e2]));
        }
        __syncthreads();
        if (tid < 64) {
            float v = lds32f(smb + OFF_CSP + tid * 4)
                    + lds32f(smb + OFF_CSP + (64 + tid) * 4)
                    + lds32f(smb + OFF_CSP + (128 + tid) * 4)
                    + lds32f(smb + OFF_CSP + (192 + tid) * 4);
            g_cpart[(size_t)blockIdx.x * SEQX + t * TN + tid] = v;
        }
    }
}

// ---------------------------------------------------------------------------
// out GEMV: g_opart[b][ch][d] = sum over x-chunk of c_x * X[x][d]
// ---------------------------------------------------------------------------
__global__ void outgemv_kernel(const float* __restrict__ Xg)
{
    __shared__ float cbuf[256];
    __shared__ float acc2[256];
    const int b  = blockIdx.x >> 3;
    const int ch = blockIdx.x & 7;
    const int tid = threadIdx.x;
    {
        float s = 0.f;
        const int x = ch * 256 + tid;
        #pragma unroll
        for (int y = 0; y < YB; ++y)
            s += g_cpart[(size_t)(b * YB + y) * SEQX + x];
        cbuf[tid] = s;
    }
    __syncthreads();
    const int d = tid & 127;
    const int h = tid >> 7;
    const float* xp = Xg + ((size_t)b * SEQX + ch * 256 + h * 128) * DIM + d;
    float acc = 0.f;
    #pragma unroll 8
    for (int j = 0; j < 128; ++j)
        acc += cbuf[h * 128 + j] * xp[(size_t)j * DIM];
    acc2[tid] = acc;
    __syncthreads();
    if (tid < 128)
        g_opart[(size_t)(b * 8 + ch) * DIM + tid] = acc2[tid] + acc2[tid + 128];
}

__global__ void outfinal_kernel(float* __restrict__ out)
{
    int b = blockIdx.x, d = threadIdx.x;
    float s = 0.f;
    #pragma unroll
    for (int ch = 0; ch < 8; ++ch)
        s += g_opart[(size_t)(b * 8 + ch) * DIM + d];
    out[(size_t)BATCH * SEQX + b * DIM + d] = s * (1.0f / SEQY);
}

// ---------------------------------------------------------------------------
// visual path (exact fp32 rank-1), unchanged from R7
// ---------------------------------------------------------------------------
__global__ void ysum_kernel(const float* __restrict__ Yg)
{
    __shared__ float buf[2 * DIM];
    int b = blockIdx.x;
    int d = threadIdx.x & 127;
    int h = threadIdx.x >> 7;
    const float* p = Yg + ((size_t)b * SEQY + h) * DIM + d;
    float s0 = 0.f, s1 = 0.f, s2 = 0.f, s3 = 0.f;
    for (int y = 0; y < SEQY / 2; y += 4) {
        s0 += p[(size_t)(2 * (y + 0)) * DIM];
        s1 += p[(size_t)(2 * (y + 1)) * DIM];
        s2 += p[(size_t)(2 * (y + 2)) * DIM];
        s3 += p[(size_t)(2 * (y + 3)) * DIM];
    }
    buf[h * DIM + d] = (s0 + s1) + (s2 + s3);
    __syncthreads();
    if (h == 0) g_ysum[b * DIM + d] = buf[d] + buf[DIM + d];
}

__global__ void visual_kernel(const float* __restrict__ Xg, float* __restrict__ out)
{
    __shared__ float ys[DIM];
    const int bpb = SEQX / 8;
    int b  = blockIdx.x / bpb;
    int x0 = (blockIdx.x % bpb) * 8;
    if (threadIdx.x < DIM) ys[threadIdx.x] = g_ysum[b * DIM + threadIdx.x];
    __syncthreads();
    int w    = threadIdx.x >> 5;
    int lane = threadIdx.x & 31;
    int x    = x0 + w;
    const float* xp = Xg + ((size_t)b * SEQX + x) * DIM + lane * 4;
    float4 xv = *reinterpret_cast<const float4*>(xp);
    float4 yv = *reinterpret_cast<const float4*>(ys + lane * 4);
    float sdot = xv.x * yv.x + xv.y * yv.y + xv.z * yv.z + xv.w * yv.w;
    #pragma unroll
    for (int o = 16; o > 0; o >>= 1)
        sdot += __shfl_xor_sync(0xffffffffu, sdot, o);
    if (lane == 0) out[(size_t)b * SEQX + x] = sdot * (1.0f / SEQY);
}

extern "C" void kernel_launch(void* const* d_in, const int* in_sizes, int n_in,
                              void* d_out, int out_size)
{
    const float* X = (const float*)d_in[0];
    const float* Y = (const float*)d_in[1];
    float* out = (float*)d_out;
    (void)in_sizes; (void)n_in; (void)out_size;

    cudaFuncSetAttribute(attn_hmma_kernel,
                         cudaFuncAttributeMaxDynamicSharedMemorySize, SM_BYTES);

    attn_hmma_kernel<<<BATCH * YB, NTHREADS, SM_BYTES>>>(X, Y);
    ysum_kernel<<<BATCH, 256>>>(Y);
    visual_kernel<<<BATCH * SEQX / 8, 256>>>(X, out);
    outgemv_kernel<<<BATCH * 8, 256>>>(X);
    outfinal_kernel<<<BATCH, DIM>>>(out);
}

// round 14
// speedup vs baseline: 3.2792x; 1.4175x over previous
#include <cuda_runtime.h>
#include <cuda_bf16.h>
#include <cstdint>

#define BATCH 16
#define SEQY 2048
#define SEQX 2048
#define DIM 128
#define TN 64                   // x cols per tile
#define NT (SEQX / TN)          // 32 x-tiles
#define YB (SEQY / 128)         // 16 y-blocks per batch
#define NTHREADS 256

#define PITCH 272u              // bytes per bf16 row (128 bf16 + 8 pad)

// smem byte offsets
#define OFF_YHI   0u
#define OFF_YLO   34816u        // 128*272
#define OFF_X0    69632u        // X buf0 hi
#define OFF_X1    104448u       // X buf1 hi
#define DLT_XLO   17408u        // hi->lo within an X buf (64*272)
#define DLT_YLO   34816u
#define OFF_RED   OFF_X0        // reuse buf0 for epilogue reduce (8*128 f32)
#define SM_BYTES  139264u

__device__ float g_partial[BATCH * YB * DIM];
__device__ float g_ysum[BATCH * DIM];

static __device__ __forceinline__ uint32_t smem_u32_of(const void* p) {
    uint32_t a;
    asm("{ .reg .u64 t; cvta.to.shared.u64 t, %1; cvt.u32.u64 %0, t; }" : "=r"(a) : "l"(p));
    return a;
}
static __device__ __forceinline__ void sts32(uint32_t a, uint32_t v) {
    asm volatile("st.shared.b32 [%0], %1;" :: "r"(a), "r"(v));
}
static __device__ __forceinline__ float lds32f(uint32_t a) {
    float v;
    asm volatile("ld.shared.f32 %0, [%1];" : "=f"(v) : "r"(a));
    return v;
}

// word: low half = even-d elem (lower addr), high = odd
static __device__ __forceinline__ uint32_t hi_pack(float a, float b) {
    uint32_t r;
    asm("prmt.b32 %0, %1, %2, 0x7632;" : "=r"(r)
        : "r"(__float_as_uint(a)), "r"(__float_as_uint(b)));
    return r;
}
static __device__ __forceinline__ uint32_t lo_pack(float a, float b) {
    float ah = __uint_as_float(__float_as_uint(a) & 0xffff0000u);
    float bh = __uint_as_float(__float_as_uint(b) & 0xffff0000u);
    uint32_t r;
    asm("cvt.rn.bf16x2.f32 %0, %1, %2;" : "=r"(r) : "f"(b - bh), "f"(a - ah));
    return r;
}
static __device__ __forceinline__ uint32_t pack_f2(float lo, float hi) {
    uint32_t r;
    asm("cvt.rn.satfinite.bf16x2.f32 %0, %1, %2;" : "=r"(r) : "f"(hi), "f"(lo));
    return r;
}

#define LDSM4(R, a)                                                          \
    asm volatile("ldmatrix.sync.aligned.m8n8.x4.shared.b16 {%0,%1,%2,%3}, [%4];" \
        : "=r"((R)[0]), "=r"((R)[1]), "=r"((R)[2]), "=r"((R)[3]) : "r"(a))
#define LDSM4T(R, a)                                                         \
    asm volatile("ldmatrix.sync.aligned.m8n8.x4.trans.shared.b16 {%0,%1,%2,%3}, [%4];" \
        : "=r"((R)[0]), "=r"((R)[1]), "=r"((R)[2]), "=r"((R)[3]) : "r"(a))

#define MMA(D, A, B0, B1)                                                    \
    asm volatile("mma.sync.aligned.m16n8k16.row.col.f32.bf16.bf16.f32 "      \
        "{%0,%1,%2,%3}, {%4,%5,%6,%7}, {%8,%9}, {%0,%1,%2,%3};"              \
        : "+f"((D)[0]), "+f"((D)[1]), "+f"((D)[2]), "+f"((D)[3])             \
        : "r"((A)[0]), "r"((A)[1]), "r"((A)[2]), "r"((A)[3]),                \
          "r"(B0), "r"(B1))

// store prefetched X tile (regs) -> bf16 hi/lo smem
static __device__ __forceinline__ void store_x(const float4* pf, uint32_t xbase,
                                               int tid) {
    const uint32_t hb = xbase + (uint32_t)(tid >> 2) * PITCH +
                        (uint32_t)(tid & 3) * 64u;
    #pragma unroll
    for (int i = 0; i < 8; ++i) {
        float4 v = pf[i];
        sts32(hb + i * 8,                 hi_pack(v.x, v.y));
        sts32(hb + i * 8 + 4,             hi_pack(v.z, v.w));
        sts32(hb + i * 8 + DLT_XLO,       lo_pack(v.x, v.y));
        sts32(hb + i * 8 + 4 + DLT_XLO,   lo_pack(v.z, v.w));
    }
}

// ---------------------------------------------------------------------------
// Flash kernel: blockIdx = b*16 + yb. 8 warps, each m16 x n64, O in regs.
// ---------------------------------------------------------------------------
__global__ void __launch_bounds__(NTHREADS, 1)
attn_flash_kernel(const float* __restrict__ Xg, const float* __restrict__ Yg)
{
    extern __shared__ char smem[];
    const uint32_t smb = smem_u32_of(smem);
    const int tid  = threadIdx.x;
    const int lane = tid & 31;
    const int w    = tid >> 5;
    const int b    = blockIdx.x >> 4;
    const int yb   = blockIdx.x & 15;
    const float* Xb = Xg + (size_t)b * SEQX * DIM;

    // ---- Y prologue: 128x128 fp32 -> bf16 hi/lo smem ----
    {
        const int row = tid >> 1;
        const int kc  = (tid & 1) * 64;
        const float4* gp = reinterpret_cast<const float4*>(
            Yg + ((size_t)(b * SEQY + yb * 128 + row)) * DIM + kc);
        uint32_t hb = smb + OFF_YHI + (uint32_t)row * PITCH + (uint32_t)kc * 2;
        #pragma unroll
        for (int i = 0; i < 16; ++i) {
            float4 v = gp[i];
            sts32(hb + i * 8,               hi_pack(v.x, v.y));
            sts32(hb + i * 8 + 4,           hi_pack(v.z, v.w));
            sts32(hb + i * 8 + DLT_YLO,     lo_pack(v.x, v.y));
            sts32(hb + i * 8 + 4 + DLT_YLO, lo_pack(v.z, v.w));
        }
    }

    // ---- X tile 0 prefetch + store ----
    const int prow = tid >> 2;
    const int pdc  = (tid & 3) * 32;
    float4 pf[8];
    {
        const float4* gp = reinterpret_cast<const float4*>(Xb + prow * DIM + pdc);
        #pragma unroll
        for (int i = 0; i < 8; ++i) pf[i] = gp[i];
        store_x(pf, smb + OFF_X0, tid);
    }
    __syncthreads();

    // ldmatrix lane-address components
    const uint32_t aY = smb + OFF_YHI +
        (uint32_t)(w * 16 + (lane & 15)) * PITCH + (uint32_t)(lane >> 4) * 16u;
    const uint32_t bs_row = (uint32_t)((lane & 7) + ((lane >> 4) << 3)) * PITCH +
                            (uint32_t)(((lane >> 3) & 1) << 4);        // S-B
    const uint32_t pv_row = (uint32_t)((lane & 7) + (((lane >> 3) & 1) << 3)) * PITCH +
                            (uint32_t)((lane >> 4) << 4);              // PV-B (trans)

    float O[16][4];
    #pragma unroll
    for (int n = 0; n < 16; ++n)
        #pragma unroll
        for (int e = 0; e < 4; ++e) O[n][e] = 0.f;
    float rs0 = 0.f, rs1 = 0.f;

    for (int t = 0; t < NT; ++t) {
        const uint32_t XH = smb + ((t & 1) ? OFF_X1 : OFF_X0);

        // prefetch tile t+1 (gmem -> regs); latency hidden by S compute
        if (t + 1 < NT) {
            const float4* gp = reinterpret_cast<const float4*>(
                Xb + (size_t)(t + 1) * TN * DIM + prow * DIM + pdc);
            #pragma unroll
            for (int i = 0; i < 8; ++i) pf[i] = gp[i];
        }

        // ---- S = Y(16) @ X(64)^T, 3-pass bf16 split ----
        float S[8][4];
        #pragma unroll
        for (int n = 0; n < 8; ++n)
            #pragma unroll
            for (int e = 0; e < 4; ++e) S[n][e] = 0.f;

        #pragma unroll
        for (int ks = 0; ks < 8; ++ks) {
            uint32_t Ah[4], Al[4];
            LDSM4(Ah, aY + ks * 32);
            LDSM4(Al, aY + DLT_YLO + ks * 32);
            #pragma unroll
            for (int q = 0; q < 4; ++q) {
                uint32_t Bh[4], Bl[4];
                uint32_t ba = XH + (uint32_t)(q * 16) * PITCH + bs_row + ks * 32;
                LDSM4(Bh, ba);
                LDSM4(Bl, ba + DLT_XLO);
                MMA(S[2 * q],     Ah, Bh[0], Bh[1]);
                MMA(S[2 * q],     Ah, Bl[0], Bl[1]);
                MMA(S[2 * q],     Al, Bh[0], Bh[1]);
                MMA(S[2 * q + 1], Ah, Bh[2], Bh[3]);
                MMA(S[2 * q + 1], Ah, Bl[2], Bl[3]);
                MMA(S[2 * q + 1], Al, Bh[2], Bh[3]);
            }
        }

        // store prefetched tile into the other buffer
        if (t + 1 < NT)
            store_x(pf, smb + (((t + 1) & 1) ? OFF_X1 : OFF_X0), tid);

        // ---- exp -> P hi/lo fragments (A operands for PV), row-sum update ----
        uint32_t Phi[4][4], Plo[4][4];
        #pragma unroll
        for (int n = 0; n < 8; ++n) {
            float e0 = __expf(S[n][0]);
            float e1 = __expf(S[n][1]);
            float e2 = __expf(S[n][2]);
            float e3 = __expf(S[n][3]);
            rs0 += e0 + e1;
            rs1 += e2 + e3;
            const int j = n >> 1, h = n & 1;
            uint32_t p01 = pack_f2(e0, e1);
            uint32_t p23 = pack_f2(e2, e3);
            Phi[j][2 * h]     = p01;
            Phi[j][2 * h + 1] = p23;
            // residuals: e - rn_bf16(e), packed bf16
            float r0 = e0 - __uint_as_float(p01 << 16);
            float r1 = e1 - __uint_as_float(p01 & 0xffff0000u);
            float r2 = e2 - __uint_as_float(p23 << 16);
            float r3 = e3 - __uint_as_float(p23 & 0xffff0000u);
            Plo[j][2 * h]     = pack_f2(r0, r1);
            Plo[j][2 * h + 1] = pack_f2(r2, r3);
        }

        // ---- O += Phi@Xhi + Phi@Xlo + Plo@Xhi  (16x64 @ 64x128) ----
        #pragma unroll
        for (int j = 0; j < 4; ++j) {
            #pragma unroll
            for (int q = 0; q < 8; ++q) {
                uint32_t Bh[4], Bl[4];
                uint32_t ba = XH + (uint32_t)(j * 16) * PITCH + pv_row + q * 32;
                LDSM4T(Bh, ba);
                LDSM4T(Bl, ba + DLT_XLO);
                MMA(O[2 * q],     Phi[j], Bh[0], Bh[1]);
                MMA(O[2 * q],     Phi[j], Bl[0], Bl[1]);
                MMA(O[2 * q],     Plo[j], Bh[0], Bh[1]);
                MMA(O[2 * q + 1], Phi[j], Bh[2], Bh[3]);
                MMA(O[2 * q + 1], Phi[j], Bl[2], Bl[3]);
                MMA(O[2 * q + 1], Plo[j], Bh[2], Bh[3]);
            }
        }
        __syncthreads();
    }

    // ---- epilogue: per-warp sum_y O/l -> smem -> g_partial ----
    rs0 += __shfl_xor_sync(0xffffffffu, rs0, 1);
    rs0 += __shfl_xor_sync(0xffffffffu, rs0, 2);
    rs1 += __shfl_xor_sync(0xffffffffu, rs1, 1);
    rs1 += __shfl_xor_sync(0xffffffffu, rs1, 2);
    const float li0 = 1.0f / rs0;
    const float li1 = 1.0f / rs1;
    #pragma unroll
    for (int n = 0; n < 16; ++n) {
        float v0 = O[n][0] * li0 + O[n][2] * li1;
        float v1 = O[n][1] * li0 + O[n][3] * li1;
        v0 += __shfl_xor_sync(0xffffffffu, v0, 4);
        v0 += __shfl_xor_sync(0xffffffffu, v0, 8);
        v0 += __shfl_xor_sync(0xffffffffu, v0, 16);
        v1 += __shfl_xor_sync(0xffffffffu, v1, 4);
        v1 += __shfl_xor_sync(0xffffffffu, v1, 8);
        v1 += __shfl_xor_sync(0xffffffffu, v1, 16);
        if (lane < 4) {
            uint32_t ra = smb + OFF_RED + (uint32_t)(w * 128 + n * 8 + lane * 2) * 4;
            sts32(ra,     __float_as_uint(v0));
            sts32(ra + 4, __float_as_uint(v1));
        }
    }
    __syncthreads();
    if (tid < DIM) {
        float s = 0.f;
        #pragma unroll
        for (int ww = 0; ww < 8; ++ww)
            s += lds32f(smb + OFF_RED + (uint32_t)(ww * 128 + tid) * 4);
        g_partial[blockIdx.x * DIM + tid] = s;
    }
}

// ---------------------------------------------------------------------------
// visual path (exact fp32 rank-1)
// ---------------------------------------------------------------------------
__global__ void ysum_kernel(const float* __restrict__ Yg)
{
    __shared__ float buf[2 * DIM];
    int b = blockIdx.x;
    int d = threadIdx.x & 127;
    int h = threadIdx.x >> 7;
    const float* p = Yg + ((size_t)b * SEQY + h) * DIM + d;
    float s0 = 0.f, s1 = 0.f, s2 = 0.f, s3 = 0.f;
    for (int y = 0; y < SEQY / 2; y += 4) {
        s0 += p[(size_t)(2 * (y + 0)) * DIM];
        s1 += p[(size_t)(2 * (y + 1)) * DIM];
        s2 += p[(size_t)(2 * (y + 2)) * DIM];
        s3 += p[(size_t)(2 * (y + 3)) * DIM];
    }
    buf[h * DIM + d] = (s0 + s1) + (s2 + s3);
    __syncthreads();
    if (h == 0) g_ysum[b * DIM + d] = buf[d] + buf[DIM + d];
}

__global__ void visual_kernel(const float* __restrict__ Xg, float* __restrict__ out)
{
    __shared__ float ys[DIM];
    const int bpb = SEQX / 8;
    int b  = blockIdx.x / bpb;
    int x0 = (blockIdx.x % bpb) * 8;
    if (threadIdx.x < DIM) ys[threadIdx.x] = g_ysum[b * DIM + threadIdx.x];
    __syncthreads();
    int w    = threadIdx.x >> 5;
    int lane = threadIdx.x & 31;
    int x    = x0 + w;
    const float* xp = Xg + ((size_t)b * SEQX + x) * DIM + lane * 4;
    float4 xv = *reinterpret_cast<const float4*>(xp);
    float4 yv = *reinterpret_cast<const float4*>(ys + lane * 4);
    float sdot = xv.x * yv.x + xv.y * yv.y + xv.z * yv.z + xv.w * yv.w;
    #pragma unroll
    for (int o = 16; o > 0; o >>= 1)
        sdot += __shfl_xor_sync(0xffffffffu, sdot, o);
    if (lane == 0) out[(size_t)b * SEQX + x] = sdot * (1.0f / SEQY);
}

__global__ void outfinal_kernel(float* __restrict__ out)
{
    int b = blockIdx.x, d = threadIdx.x;
    float s = 0.f;
    #pragma unroll
    for (int g = 0; g < YB; ++g)
        s += g_partial[(b * YB + g) * DIM + d];
    out[(size_t)BATCH * SEQX + b * DIM + d] = s * (1.0f / SEQY);
}

extern "C" void kernel_launch(void* const* d_in, const int* in_sizes, int n_in,
                              void* d_out, int out_size)
{
    const float* X = (const float*)d_in[0];
    const float* Y = (const float*)d_in[1];
    float* out = (float*)d_out;
    (void)in_sizes; (void)n_in; (void)out_size;

    cudaFuncSetAttribute(attn_flash_kernel,
                         cudaFuncAttributeMaxDynamicSharedMemorySize, SM_BYTES);

    attn_flash_kernel<<<BATCH * YB, NTHREADS, SM_BYTES>>>(X, Y);
    ysum_kernel<<<BATCH, 256>>>(Y);
    visual_kernel<<<BATCH * SEQX / 8, 256>>>(X, out);
    outfinal_kernel<<<BATCH, DIM>>>(out);
}